// round 17
// baseline (speedup 1.0000x reference)
#include <cuda_runtime.h>
#include <cuda_bf16.h>
#include <cstdint>

#define N_NODES 100000
#define N_EDGES 600000
#define N_GRAPHS 2000
#define HID 128
#define LAYERS 6
#define SCAN_BLOCKS 98   // ceil(100000/1024)

// Scratch buffers (allocation-free rule: __device__ globals)
__device__ float g_x[(size_t)N_NODES * HID];
__device__ float g_xin[(size_t)N_NODES * HID];
__device__ float g_cnt[N_GRAPHS];
// CSR scratch
__device__ int g_deg[N_NODES];
__device__ int g_rpp[N_NODES];
__device__ int g_bsum[128];
__device__ int g_rowptr[N_NODES + 1];
__device__ int g_cursor[N_NODES];
__device__ int g_csr[N_EDGES];
// Pre-converted W in fragment-ready bf16 hi/lo layout: [12 mats][8192 u32]
__device__ uint32_t g_whi[12 * 8192];
__device__ uint32_t g_wlo[12 * 8192];

// pack two floats into bf16x2: low half = e0, high half = e1
static __device__ __forceinline__ uint32_t pack_bf16x2(float e0, float e1) {
    uint32_t r;
    asm("cvt.rn.bf16x2.f32 %0, %1, %2;" : "=r"(r) : "f"(e1), "f"(e0));
    return r;
}

#define MMA_BF16(d, a, b)                                                     \
    asm volatile(                                                             \
        "mma.sync.aligned.m16n8k16.row.col.f32.bf16.bf16.f32 "                \
        "{%0,%1,%2,%3}, {%4,%5,%6,%7}, {%8,%9}, {%0,%1,%2,%3};"               \
        : "+f"((d)[0]), "+f"((d)[1]), "+f"((d)[2]), "+f"((d)[3])              \
        : "r"((a).x), "r"((a).y), "r"((a).z), "r"((a).w),                     \
          "r"((b).x), "r"((b).y))

// ---------------------------------------------------------------------------
// W pre-conversion: fp32 [128k x 128n] -> fragment-ready bf16 hi/lo.
// ---------------------------------------------------------------------------
__global__ void wconv_kernel(const float* __restrict__ W1,
                             const float* __restrict__ W2) {
    int mat = blockIdx.x;            // l*2 + s
    int l = mat >> 1, s = mat & 1;
    const float* W = (s ? W2 : W1) + (size_t)l * HID * HID;
    for (int i = threadIdx.x; i < 8192; i += 256) {
        int tile = i >> 6;
        int w    = i & 63;
        int lane = w >> 1, reg = w & 1;
        int kt = tile >> 4, nt = tile & 15;
        int k = kt * 16 + reg * 8 + (lane & 3) * 2;
        int n = nt * 8 + (lane >> 2);
        float x0 = W[k * HID + n];
        float x1 = W[(k + 1) * HID + n];
        uint32_t hp = pack_bf16x2(x0, x1);
        float h0 = __uint_as_float(hp << 16);
        float h1 = __uint_as_float(hp & 0xffff0000u);
        uint32_t lp = pack_bf16x2(x0 - h0, x1 - h1);
        g_whi[mat * 8192 + i] = hp;
        g_wlo[mat * 8192 + i] = lp;
    }
}

// ---------------------------------------------------------------------------
// CSR build: degree histogram -> 3-kernel exclusive scan -> slot fill
// ---------------------------------------------------------------------------
__global__ void deg_kernel(const int* __restrict__ dst) {
    int e = blockIdx.x * blockDim.x + threadIdx.x;
    if (e < N_EDGES) atomicAdd(&g_deg[__ldg(dst + e)], 1);
}

__global__ void scan1_kernel() {
    __shared__ int s[1024];
    int t = threadIdx.x, b = blockIdx.x;
    int idx = b * 1024 + t;
    int v = (idx < N_NODES) ? g_deg[idx] : 0;
    s[t] = v;
    __syncthreads();
#pragma unroll
    for (int off = 1; off < 1024; off <<= 1) {
        int u = (t >= off) ? s[t - off] : 0;
        __syncthreads();
        s[t] += u;
        __syncthreads();
    }
    if (idx < N_NODES) g_rpp[idx] = s[t] - v;    // exclusive within block
    if (t == 1023) g_bsum[b] = s[1023];
}

__global__ void scan2_kernel() {   // 1 block, 128 threads
    __shared__ int s[128];
    int t = threadIdx.x;
    int v = (t < SCAN_BLOCKS) ? g_bsum[t] : 0;
    s[t] = v;
    __syncthreads();
#pragma unroll
    for (int off = 1; off < 128; off <<= 1) {
        int u = (t >= off) ? s[t - off] : 0;
        __syncthreads();
        s[t] += u;
        __syncthreads();
    }
    if (t < SCAN_BLOCKS) g_bsum[t] = s[t] - v;   // exclusive
    if (t == 127) g_rowptr[N_NODES] = s[127];    // total (= N_EDGES)
}

__global__ void scan3_kernel() {
    int idx = blockIdx.x * blockDim.x + threadIdx.x;
    if (idx >= N_NODES) return;
    int r = g_rpp[idx] + g_bsum[idx >> 10];
    g_rowptr[idx] = r;
    g_cursor[idx] = r;
}

__global__ void fill_kernel(const int* __restrict__ src,
                            const int* __restrict__ dst) {
    int e = blockIdx.x * blockDim.x + threadIdx.x;
    if (e >= N_EDGES) return;
    int slot = atomicAdd(&g_cursor[__ldg(dst + e)], 1);
    g_csr[slot] = __ldg(src + e);
}

// ---------------------------------------------------------------------------
// Embedding gather
// ---------------------------------------------------------------------------
__global__ void embed_kernel(const int* __restrict__ tok,
                             const float* __restrict__ emb,
                             float* __restrict__ x) {
    int i = blockIdx.x * blockDim.x + threadIdx.x;
    if (i >= N_NODES * 32) return;
    int node = i >> 5;
    int c    = i & 31;
    int t = __ldg(tok + node);
    ((float4*)x)[(size_t)node * 32 + c] =
        ((const float4*)emb)[(size_t)t * 32 + c];
}

__global__ void zero_kernel(float4* __restrict__ p, int n4) {
    int i = blockIdx.x * blockDim.x + threadIdx.x;
    if (i < n4) p[i] = make_float4(0.f, 0.f, 0.f, 0.f);
}

// ---------------------------------------------------------------------------
// Fused layer: xout = relu(relu((x + A_adj x) @ W1 + b1) @ W2 + b2)
// CTA 256 threads (8 warps), tile M=128, N=128.
// Stage-1 A-load does the CSR gather in-kernel: warp w gathers rows
// w*16..w*16+15; lane owns float4 c4=lane of the 128-wide row. The gathered
// sum goes straight into bf16 hi/lo fragment smem. Requires ping-pong x
// buffers (later-wave CTAs read old rows).
// 3-pass bf16 split per MMA tile. Dynamic smem 64KB -> 2 CTAs/SM.
// ---------------------------------------------------------------------------
__global__ __launch_bounds__(256, 2) void layer_kernel(
    const float* __restrict__ xsrc,
    const uint32_t* __restrict__ w1h, const uint32_t* __restrict__ w1l,
    const float* __restrict__ b1,
    const uint32_t* __restrict__ w2h, const uint32_t* __restrict__ w2l,
    const float* __restrict__ b2,
    float* __restrict__ xout) {
    extern __shared__ uint32_t smu[];
    uint32_t* sAh = smu;            // [2][4096] hi frags (2 k-chunks)
    uint32_t* sAl = smu + 8192;     // [2][4096] lo frags

    int tid  = threadIdx.x;
    int lane = tid & 31;
    int wid  = tid >> 5;
    int wm = wid >> 1;               // 0..3
    int wn = wid & 1;                // 0..1
    int row0 = blockIdx.x * 128;

    // ---- Stage-1: fused CSR gather -> frag smem ----
    // Frag mapping for this lane (c4 = lane), constant across rows:
    {
        int ck = lane >> 4;
        int kl = (lane & 15) * 4;            // k within 64-chunk
        int l0b = (kl & 7) >> 1;             // lane0 k-part
        int regk = ((kl & 15) >> 3) << 1;
        int tk  = (kl >> 4) << 3;            // k-tile * 8
#pragma unroll 2
        for (int rr = 0; rr < 16; rr++) {
            int r = wid * 16 + rr;
            int row = row0 + r;
            float4 v = make_float4(0.f, 0.f, 0.f, 0.f);
            if (row < N_NODES) {
                v = ((const float4*)xsrc)[(size_t)row * 32 + lane];
                int beg = __ldg(&g_rowptr[row]);
                int end = __ldg(&g_rowptr[row + 1]);
                int e = beg;
                for (; e + 1 < end; e += 2) {
                    int s0 = __ldg(&g_csr[e]);
                    int s1 = __ldg(&g_csr[e + 1]);
                    float4 v0 = ((const float4*)xsrc)[(size_t)s0 * 32 + lane];
                    float4 v1 = ((const float4*)xsrc)[(size_t)s1 * 32 + lane];
                    v.x += v0.x + v1.x; v.y += v0.y + v1.y;
                    v.z += v0.z + v1.z; v.w += v0.w + v1.w;
                }
                if (e < end) {
                    int s0 = __ldg(&g_csr[e]);
                    float4 v0 = ((const float4*)xsrc)[(size_t)s0 * 32 + lane];
                    v.x += v0.x; v.y += v0.y; v.z += v0.z; v.w += v0.w;
                }
            }
            int lane0 = (r & 7) * 4 + l0b;
            int reg   = ((r & 15) >> 3) + regk;
            int tile  = tk + (r >> 4);
            int base  = ck * 4096 + tile * 128 + reg;
            uint32_t hp0 = pack_bf16x2(v.x, v.y);
            uint32_t hp1 = pack_bf16x2(v.z, v.w);
            float h0 = __uint_as_float(hp0 << 16);
            float h1 = __uint_as_float(hp0 & 0xffff0000u);
            float h2 = __uint_as_float(hp1 << 16);
            float h3 = __uint_as_float(hp1 & 0xffff0000u);
            sAh[base + lane0 * 4]       = hp0;
            sAl[base + lane0 * 4]       = pack_bf16x2(v.x - h0, v.y - h1);
            sAh[base + (lane0 + 1) * 4] = hp1;
            sAl[base + (lane0 + 1) * 4] = pack_bf16x2(v.z - h2, v.w - h3);
        }
    }
    __syncthreads();

    float acc[2][8][4];
#pragma unroll
    for (int mt = 0; mt < 2; mt++)
#pragma unroll
        for (int j = 0; j < 8; j++)
#pragma unroll
            for (int c = 0; c < 4; c++) acc[mt][j][c] = 0.f;

    // ---- Stage-1 compute: (x + agg) @ W1 ----
#pragma unroll
    for (int ktg = 0; ktg < 8; ktg++) {
        int ck = ktg >> 2, kt = ktg & 3;
        uint4 ah[2], al[2];
#pragma unroll
        for (int mt = 0; mt < 2; mt++) {
            int tile = ck * 4096 + (kt * 8 + wm * 2 + mt) * 128;
            ah[mt] = *(const uint4*)&sAh[tile + lane * 4];
            al[mt] = *(const uint4*)&sAl[tile + lane * 4];
        }
#pragma unroll
        for (int j = 0; j < 8; j++) {
            int tile = ktg * 16 + wn * 8 + j;
            uint2 bh = *(const uint2*)&w1h[tile * 64 + lane * 2];
            uint2 bl = *(const uint2*)&w1l[tile * 64 + lane * 2];
#pragma unroll
            for (int mt = 0; mt < 2; mt++) {
                MMA_BF16(acc[mt][j], ah[mt], bh);
                MMA_BF16(acc[mt][j], ah[mt], bl);
                MMA_BF16(acc[mt][j], al[mt], bh);
            }
        }
    }
    __syncthreads();   // frag smem fully consumed; safe to overwrite

    // ---- Epilogue 1: h = relu(acc + b1) -> frag smem (hi/lo) ----
#pragma unroll
    for (int mt = 0; mt < 2; mt++) {
        int rb = (wm * 2 + mt) * 16 + (lane >> 2);   // local row (<8 within tile)
#pragma unroll
        for (int j = 0; j < 8; j++) {
            int col = (wn * 8 + j) * 8 + (lane & 3) * 2;
            float2 bb = *(const float2*)(b1 + col);
            float h00 = fmaxf(acc[mt][j][0] + bb.x, 0.f);
            float h01 = fmaxf(acc[mt][j][1] + bb.y, 0.f);
            float h10 = fmaxf(acc[mt][j][2] + bb.x, 0.f);
            float h11 = fmaxf(acc[mt][j][3] + bb.y, 0.f);
            int ck2 = col >> 6;
            int kl  = col & 63;
            int lane0 = (rb & 7) * 4 + ((kl & 7) >> 1);
            int reg   = (((kl & 15) >> 3) << 1);     // rb&15 < 8 -> row bit 0
            int tile  = ((kl >> 4) << 3) + (rb >> 4);
            int idx0  = ck2 * 4096 + tile * 128 + reg + lane0 * 4;
            uint32_t hp0 = pack_bf16x2(h00, h01);
            float e0 = __uint_as_float(hp0 << 16);
            float e1 = __uint_as_float(hp0 & 0xffff0000u);
            sAh[idx0] = hp0;
            sAl[idx0] = pack_bf16x2(h00 - e0, h01 - e1);
            uint32_t hp1 = pack_bf16x2(h10, h11);     // row rb+8 -> reg+1
            float e2 = __uint_as_float(hp1 << 16);
            float e3 = __uint_as_float(hp1 & 0xffff0000u);
            sAh[idx0 + 1] = hp1;
            sAl[idx0 + 1] = pack_bf16x2(h10 - e2, h11 - e3);
        }
    }
    __syncthreads();

    // ---- Stage-2 compute: h @ W2 ----
#pragma unroll
    for (int mt = 0; mt < 2; mt++)
#pragma unroll
        for (int j = 0; j < 8; j++)
#pragma unroll
            for (int c = 0; c < 4; c++) acc[mt][j][c] = 0.f;

#pragma unroll
    for (int ktg = 0; ktg < 8; ktg++) {
        int ck = ktg >> 2, kt = ktg & 3;
        uint4 ah[2], al[2];
#pragma unroll
        for (int mt = 0; mt < 2; mt++) {
            int tile = ck * 4096 + (kt * 8 + wm * 2 + mt) * 128;
            ah[mt] = *(const uint4*)&sAh[tile + lane * 4];
            al[mt] = *(const uint4*)&sAl[tile + lane * 4];
        }
#pragma unroll
        for (int j = 0; j < 8; j++) {
            int tile = ktg * 16 + wn * 8 + j;
            uint2 bh = *(const uint2*)&w2h[tile * 64 + lane * 2];
            uint2 bl = *(const uint2*)&w2l[tile * 64 + lane * 2];
#pragma unroll
            for (int mt = 0; mt < 2; mt++) {
                MMA_BF16(acc[mt][j], ah[mt], bh);
                MMA_BF16(acc[mt][j], ah[mt], bl);
                MMA_BF16(acc[mt][j], al[mt], bh);
            }
        }
    }

    // ---- Epilogue 2: xout = relu(acc + b2), float2 stores ----
    int r_in = lane >> 2;
    int c2   = (lane & 3) * 2;
#pragma unroll
    for (int mt = 0; mt < 2; mt++) {
        int rb = row0 + (wm * 2 + mt) * 16 + r_in;
#pragma unroll
        for (int j = 0; j < 8; j++) {
            int col = (wn * 8 + j) * 8 + c2;
            float2 bb = *(const float2*)(b2 + col);
            if (rb < N_NODES) {
                float2 o;
                o.x = fmaxf(acc[mt][j][0] + bb.x, 0.f);
                o.y = fmaxf(acc[mt][j][1] + bb.y, 0.f);
                *(float2*)(xout + (size_t)rb * HID + col) = o;
            }
            if (rb + 8 < N_NODES) {
                float2 o;
                o.x = fmaxf(acc[mt][j][2] + bb.x, 0.f);
                o.y = fmaxf(acc[mt][j][3] + bb.y, 0.f);
                *(float2*)(xout + (size_t)(rb + 8) * HID + col) = o;
            }
        }
    }
}

// ---------------------------------------------------------------------------
// Global mean pool
// ---------------------------------------------------------------------------
__global__ void pool_kernel(const float* __restrict__ x,
                            const int* __restrict__ batch,
                            float* __restrict__ out) {
    int w = (blockIdx.x * blockDim.x + threadIdx.x) >> 5;
    if (w >= N_NODES) return;
    int lane = threadIdx.x & 31;
    int g = __ldg(batch + w);
    float4 v = ((const float4*)x)[(size_t)w * 32 + lane];
    float* p = out + (size_t)g * HID + lane * 4;
    asm volatile("red.global.add.v4.f32 [%0], {%1, %2, %3, %4};"
                 :: "l"(p), "f"(v.x), "f"(v.y), "f"(v.z), "f"(v.w)
                 : "memory");
    if (lane == 0) atomicAdd(&g_cnt[g], 1.0f);
}

__global__ void div_kernel(float* __restrict__ out) {
    int i = blockIdx.x * blockDim.x + threadIdx.x;
    if (i >= N_GRAPHS * 32) return;
    int g = i >> 5;
    float c = fmaxf(g_cnt[g], 1.0f);
    float inv = 1.0f / c;
    float4 v = ((float4*)out)[i];
    v.x *= inv; v.y *= inv; v.z *= inv; v.w *= inv;
    ((float4*)out)[i] = v;
}

// ---------------------------------------------------------------------------
extern "C" void kernel_launch(void* const* d_in, const int* in_sizes, int n_in,
                              void* d_out, int out_size) {
    const int*   tok   = (const int*)d_in[0];
    const int*   ei    = (const int*)d_in[1];   // [2, N_EDGES]
    const int*   batch = (const int*)d_in[2];
    const float* emb   = (const float*)d_in[3];
    const float* W1    = (const float*)d_in[4];
    const float* b1    = (const float*)d_in[5];
    const float* W2    = (const float*)d_in[6];
    const float* b2    = (const float*)d_in[7];
    float* out = (float*)d_out;

    const int LAYER_SMEM = 16384 * 4;   // 64KB dynamic
    cudaFuncSetAttribute(layer_kernel,
                         cudaFuncAttributeMaxDynamicSharedMemorySize, LAYER_SMEM);

    float *x, *xin, *cnt;
    int *deg;
    uint32_t *whi, *wlo;
    cudaGetSymbolAddress((void**)&x,   g_x);
    cudaGetSymbolAddress((void**)&xin, g_xin);
    cudaGetSymbolAddress((void**)&cnt, g_cnt);
    cudaGetSymbolAddress((void**)&deg, g_deg);
    cudaGetSymbolAddress((void**)&whi, g_whi);
    cudaGetSymbolAddress((void**)&wlo, g_wlo);

    const int* src = ei;
    const int* dst = ei + N_EDGES;

    // Pre-convert weights to fragment-ready bf16 hi/lo
    wconv_kernel<<<12, 256>>>(W1, W2);

    // Build CSR (edge list is constant within the launch)
    zero_kernel<<<(N_NODES / 4 + 255) / 256, 256>>>((float4*)deg, N_NODES / 4);
    deg_kernel<<<(N_EDGES + 255) / 256, 256>>>(dst);
    scan1_kernel<<<SCAN_BLOCKS, 1024>>>();
    scan2_kernel<<<1, 128>>>();
    scan3_kernel<<<(N_NODES + 255) / 256, 256>>>();
    fill_kernel<<<(N_EDGES + 255) / 256, 256>>>(src, dst);

    // Embedding
    embed_kernel<<<(N_NODES * 32 + 255) / 256, 256>>>(tok, emb, x);

    int gemm_grid = (N_NODES + 127) / 128;    // 782

    // Ping-pong: even layers x -> xin, odd layers xin -> x.
    for (int l = 0; l < LAYERS; l++) {
        const float* in  = (l & 1) ? xin : x;
        float*       outb = (l & 1) ? x : xin;
        layer_kernel<<<gemm_grid, 256, LAYER_SMEM>>>(
            in,
            whi + (size_t)(l * 2 + 0) * 8192, wlo + (size_t)(l * 2 + 0) * 8192,
            b1 + (size_t)l * HID,
            whi + (size_t)(l * 2 + 1) * 8192, wlo + (size_t)(l * 2 + 1) * 8192,
            b2 + (size_t)l * HID,
            outb);
    }

    // Mean pool (after 6 layers, result is in g_x)
    zero_kernel<<<(N_GRAPHS * 32 + 255) / 256, 256>>>((float4*)out, N_GRAPHS * 32);
    zero_kernel<<<(N_GRAPHS / 4 + 255) / 256, 256>>>((float4*)cnt, N_GRAPHS / 4);
    pool_kernel<<<(N_NODES * 32 + 255) / 256, 256>>>(x, batch, out);
    div_kernel<<<(N_GRAPHS * 32 + 255) / 256, 256>>>(out);
}